// round 15
// baseline (speedup 1.0000x reference)
#include <cuda_runtime.h>
#include <cstdint>

// Problem constants
#define B_      2
#define L_      2048
#define D_      1024
#define H_      16
#define HD_     64
#define CHUNK_  128
#define M_ROWS  (B_ * L_)          // 4096
#define QKV_N   (3 * D_)           // 3072

// Scratch (device globals — no allocation allowed)
__device__ __align__(16) float g_q[(size_t)B_ * H_ * L_ * HD_];     // [bh][l][perm(d)]
__device__ __align__(16) float g_k[(size_t)B_ * H_ * L_ * HD_];     // [bh][l][perm(d)]
__device__ __align__(16) float g_v[(size_t)B_ * H_ * HD_ * L_];     // [bh][d][l]  (UNpermuted keys)
__device__ __align__(16) float g_ctx[(size_t)B_ * L_ * D_];         // [m][perm(c)]
__device__ __align__(16) float g_xr[(size_t)M_ROWS * D_];           // [m][perm(k)]
__device__ __align__(16) float g_wqkvr[(size_t)QKV_N * D_];         // [n][perm(k)] (transposed)
__device__ __align__(16) float g_woutr[(size_t)D_ * D_];            // [n][perm(k)] (transposed)

// ===========================================================================
// Helpers
// ===========================================================================
__device__ __forceinline__ uint32_t smem_u32(const void* p) {
    uint32_t a;
    asm("{ .reg .u64 t; cvta.to.shared.u64 t, %1; cvt.u32.u64 %0, t; }" : "=r"(a) : "l"(p));
    return a;
}
__device__ __forceinline__ uint32_t f2tf(float x) {
    uint32_t r;
    asm("cvt.rna.tf32.f32 %0, %1;" : "=r"(r) : "f"(x));
    return r;
}
__device__ __forceinline__ float f2tff(float x) { return __uint_as_float(f2tf(x)); }
__device__ __forceinline__ float ex2(float x) {
    float r;
    asm("ex2.approx.ftz.f32 %0, %1;" : "=f"(r) : "f"(x));
    return r;
}

// K-dim permutation: within each 8-group, b -> ((b&3)<<1)|(b>>2)
__device__ __forceinline__ int perm_idx(int i) {
    return (i & ~7) | ((i & 3) << 1) | ((i >> 2) & 1);
}

// m16n8k8 tf32 mma: D = A*B + D  (A row-major, B col-major)
__device__ __forceinline__ void mma8(float* c, const uint32_t* a, const uint32_t* b) {
    asm volatile(
        "mma.sync.aligned.m16n8k8.row.col.f32.tf32.tf32.f32 "
        "{%0,%1,%2,%3}, {%4,%5,%6,%7}, {%8,%9}, {%0,%1,%2,%3};"
        : "+f"(c[0]), "+f"(c[1]), "+f"(c[2]), "+f"(c[3])
        : "r"(a[0]), "r"(a[1]), "r"(a[2]), "r"(a[3]), "r"(b[0]), "r"(b[1]));
}

__device__ __forceinline__ void cp16(uint32_t dst, const void* src) {
    asm volatile("cp.async.cg.shared.global [%0], [%1], 16;" :: "r"(dst), "l"(src));
}
#define CP_COMMIT() asm volatile("cp.async.commit_group;" ::: "memory")
#define CP_WAIT0()  asm volatile("cp.async.wait_group 0;" ::: "memory")
#define CP_WAIT1()  asm volatile("cp.async.wait_group 1;" ::: "memory")

// ===========================================================================
// Fused prep kernel (unchanged from R14)
// ===========================================================================
__global__ __launch_bounds__(256) void prep_kernel(
    const float* __restrict__ x, const float* __restrict__ Wqkv,
    const float* __restrict__ Wout)
{
    __shared__ float tile[32][33];
    const int bid = blockIdx.x;
    if (bid < 2048) {
        const int i = bid * 256 + threadIdx.x;
        const float4* in = (const float4*)x;
        float4* out = (float4*)g_xr;
        const float4 a = in[2 * i], b = in[2 * i + 1];
        out[2 * i]     = make_float4(f2tff(a.x), f2tff(b.x), f2tff(a.y), f2tff(b.y));
        out[2 * i + 1] = make_float4(f2tff(a.z), f2tff(b.z), f2tff(a.w), f2tff(b.w));
        return;
    }
    const float* in;
    float* out;
    int N, bx, by;
    if (bid < 5120) {
        in = Wqkv; out = g_wqkvr; N = QKV_N;
        const int id = bid - 2048; bx = id % 96; by = id / 96;
    } else {
        in = Wout; out = g_woutr; N = D_;
        const int id = bid - 5120; bx = id % 32; by = id / 32;
    }
    const int K = D_;
    const int k0 = by * 32, n0 = bx * 32;
    const int tx = threadIdx.x & 31, ty = threadIdx.x >> 5;
#pragma unroll
    for (int i = 0; i < 4; i++)
        tile[ty + 8 * i][tx] = in[(size_t)(k0 + ty + 8 * i) * N + n0 + tx];
    __syncthreads();
    const int kp = k0 + perm_idx(tx);
#pragma unroll
    for (int i = 0; i < 4; i++)
        out[(size_t)(n0 + ty + 8 * i) * K + kp] = f2tff(tile[tx][ty + 8 * i]);
}

// ===========================================================================
// tf32 mma GEMM (byte-identical to R14)
// ===========================================================================
#define GSA       40
#define GA_STG_B  (64 * GSA * 4)          // 10240
#define GB_STG_B  (128 * 32 * 4)          // 16384
#define G_STG_B   (GA_STG_B + GB_STG_B)   // 26624
#define GEMM_SMEM (2 * G_STG_B)           // 53248

template<int S>
__device__ __forceinline__ void gemm_prefetch(
    uint32_t adst, uint32_t bdst, const char* asrc, const char* bsrc, int koff)
{
#pragma unroll
    for (int i = 0; i < 4; i++)
        cp16(adst + S * G_STG_B + i * (16 * GSA * 4), asrc + koff + i * (16 * D_ * 4));
#pragma unroll
    for (int i = 0; i < 8; i++)
        cp16(bdst + S * G_STG_B + i * (16 * 128), bsrc + koff + i * (16 * D_ * 4));
}

template<int S, int KB>
__device__ __forceinline__ void load_frags(
    uint32_t af[4][4], uint32_t bf[4][2],
    uint32_t abase, uint32_t bbase, const int* xo)
{
#pragma unroll
    for (int mt = 0; mt < 4; mt++) {
        float2 lo, hi;
        asm volatile("ld.shared.v2.f32 {%0,%1}, [%2];"
            : "=f"(lo.x), "=f"(lo.y)
            : "r"(abase + S * G_STG_B + mt * (16 * GSA * 4) + KB * 32));
        asm volatile("ld.shared.v2.f32 {%0,%1}, [%2];"
            : "=f"(hi.x), "=f"(hi.y)
            : "r"(abase + S * G_STG_B + mt * (16 * GSA * 4) + 8 * GSA * 4 + KB * 32));
        af[mt][0] = __float_as_uint(lo.x);
        af[mt][1] = __float_as_uint(hi.x);
        af[mt][2] = __float_as_uint(lo.y);
        af[mt][3] = __float_as_uint(hi.y);
    }
    const uint32_t bkb = bbase + (uint32_t)xo[KB];
#pragma unroll
    for (int nt = 0; nt < 4; nt++) {
        float2 bb;
        asm volatile("ld.shared.v2.f32 {%0,%1}, [%2];"
            : "=f"(bb.x), "=f"(bb.y)
            : "r"(bkb + S * G_STG_B + nt * (8 * 128)));
        bf[nt][0] = __float_as_uint(bb.x);
        bf[nt][1] = __float_as_uint(bb.y);
    }
}

__device__ __forceinline__ void mma_burst(
    float c[4][4][4], uint32_t af[4][4], uint32_t bf[4][2])
{
#pragma unroll
    for (int mt = 0; mt < 4; mt++)
#pragma unroll
        for (int nt = 0; nt < 4; nt++)
            mma8(c[mt][nt], af[mt], bf[nt]);
}

template<int S>
__device__ __forceinline__ void gemm_stage(
    float c[4][4][4], uint32_t abase, uint32_t bbase, const int* xo)
{
    uint32_t af[2][4][4], bf[2][4][2];
    load_frags<S, 0>(af[0], bf[0], abase, bbase, xo);
    load_frags<S, 1>(af[1], bf[1], abase, bbase, xo);
    mma_burst(c, af[0], bf[0]);
    load_frags<S, 2>(af[0], bf[0], abase, bbase, xo);
    mma_burst(c, af[1], bf[1]);
    load_frags<S, 3>(af[1], bf[1], abase, bbase, xo);
    mma_burst(c, af[0], bf[0]);
    mma_burst(c, af[1], bf[1]);
}

__global__ __launch_bounds__(128, 4) void gemm_mma_kernel(
    const float* __restrict__ A, const float* __restrict__ Bt,
    const float* __restrict__ bias, float* __restrict__ C,
    int M, int N, int K, int qkv_mode)
{
    extern __shared__ __align__(16) char sm[];
    const uint32_t sb = smem_u32(sm);
    const int tid = threadIdx.x, wid = tid >> 5, lane = tid & 31;
    const int g = lane >> 2, tq = lane & 3;
    const int bm = blockIdx.y * 64, bn = blockIdx.x * 128;
    const int wn = wid * 32;

    const int pr = tid >> 3, pc = tid & 7;
    const uint32_t adst = sb + pr * (GSA * 4) + pc * 16;
    const uint32_t bdst = sb + GA_STG_B + pr * 128 +
                          (uint32_t)((pc ^ ((pr & 3) << 1)) << 4);
    const char* asrc = (const char*)(A + (size_t)(bm + pr) * K) + pc * 16;
    const char* bsrc = (const char*)(Bt + (size_t)(bn + pr) * K) + pc * 16;

    const uint32_t abase = sb + (uint32_t)(g * (GSA * 4) + tq * 8);
    const uint32_t bbase = sb + GA_STG_B + (uint32_t)((wn + g) * 128 +
                           ((tq >> 1) << 4) + (tq & 1) * 8);
    int xo[4];
#pragma unroll
    for (int kb = 0; kb < 4; kb++) xo[kb] = (kb ^ (g & 3)) << 5;

    float c[4][4][4];
#pragma unroll
    for (int mt = 0; mt < 4; mt++)
#pragma unroll
        for (int nt = 0; nt < 4; nt++)
#pragma unroll
            for (int i = 0; i < 4; i++) c[mt][nt][i] = 0.f;

    const int KT = K >> 5;
    gemm_prefetch<0>(adst, bdst, asrc, bsrc, 0);   CP_COMMIT();
    gemm_prefetch<1>(adst, bdst, asrc, bsrc, 128); CP_COMMIT();

    for (int t = 0; t < KT; t += 2) {
        const int koff2 = (t + 2) * 128;
        CP_WAIT1();
        __syncthreads();
        gemm_stage<0>(c, abase, bbase, xo);
        __syncthreads();
        if (t + 2 < KT)
            gemm_prefetch<0>(adst, bdst, asrc, bsrc, koff2);
        CP_COMMIT();
        CP_WAIT1();
        __syncthreads();
        gemm_stage<1>(c, abase, bbase, xo);
        __syncthreads();
        if (t + 3 < KT)
            gemm_prefetch<1>(adst, bdst, asrc, bsrc, koff2 + 128);
        CP_COMMIT();
    }

#pragma unroll
    for (int mt = 0; mt < 4; mt++) {
#pragma unroll
        for (int nt = 0; nt < 4; nt++) {
            const int col = bn + wn + nt * 8 + 2 * tq;
            const float b0 = bias[col], b1 = bias[col + 1];
            const int r0 = bm + mt * 16 + g;
            const int r1 = r0 + 8;
            float v00 = c[mt][nt][0] + b0, v01 = c[mt][nt][1] + b1;
            float v10 = c[mt][nt][2] + b0, v11 = c[mt][nt][3] + b1;
            if (qkv_mode) {
                v00 = f2tff(v00); v01 = f2tff(v01);
                v10 = f2tff(v10); v11 = f2tff(v11);
                const int which = col >> 10;
                const int h  = (col >> 6) & 15;
                const int dd = col & 63;
                const int bh0 = (r0 >> 11) * H_ + h, l0 = r0 & 2047;
                const int bh1 = (r1 >> 11) * H_ + h, l1 = r1 & 2047;
                if (which == 2) {
                    g_v[((size_t)bh0 * HD_ + dd) * L_ + l0]     = v00;
                    g_v[((size_t)bh0 * HD_ + dd + 1) * L_ + l0] = v01;
                    g_v[((size_t)bh1 * HD_ + dd) * L_ + l1]     = v10;
                    g_v[((size_t)bh1 * HD_ + dd + 1) * L_ + l1] = v11;
                } else {
                    float* tgt = (which == 0) ? g_q : g_k;
                    const int pd0 = perm_idx(dd), pd1 = perm_idx(dd + 1);
                    float* d0 = tgt + ((size_t)bh0 * L_ + l0) * HD_;
                    float* d1 = tgt + ((size_t)bh1 * L_ + l1) * HD_;
                    d0[pd0] = v00; d0[pd1] = v01;
                    d1[pd0] = v10; d1[pd1] = v11;
                }
            } else {
                *(float2*)(C + (size_t)r0 * N + col) = make_float2(v00, v01);
                *(float2*)(C + (size_t)r1 * N + col) = make_float2(v10, v11);
            }
        }
    }
}

// ===========================================================================
// Block-causal flash attention v3: 128 threads (4 warps) = ONE q-chunk,
// m32 warp tiles, two 64-key halves per tile. K double-buffered, V
// single-buffered -> 108.5 KB smem -> 2 CTAs/SM (phase-decoupled overlap).
// ===========================================================================
#define KS_ 72
#define VS_ 136
#define K_STAGE_B  (128 * KS_ * 4)           // 36864
#define V_STAGE_B  (HD_ * VS_ * 4)           // 34816
#define AT_VOFF    (2 * K_STAGE_B)           // 73728
#define ATTN_SMEM  (AT_VOFF + V_STAGE_B)     // 108544

__device__ __forceinline__ void attn_prefetch_k(uint32_t kdst, const float* ksrc, int tid)
{
#pragma unroll
    for (int i = 0; i < 16; i++) {
        const int idx = tid + i * 128;          // 0..2047
        const int r = idx >> 4, c = idx & 15;   // K: 128 rows x 16 chunks
        cp16(kdst + r * (KS_ * 4) + c * 16, ksrc + r * 64 + c * 4);
    }
}
__device__ __forceinline__ void attn_prefetch_v(uint32_t vdst, const float* vsrc, int tid)
{
#pragma unroll
    for (int i = 0; i < 16; i++) {
        const int idx = tid + i * 128;          // 0..2047
        const int r = idx >> 5, c = idx & 31;   // V: 64 d-rows x 32 chunks
        cp16(vdst + r * (VS_ * 4) + c * 16, vsrc + (size_t)r * L_ + c * 4);
    }
}

__global__ __launch_bounds__(128, 2) void attn_mma_kernel(float* __restrict__ ctx)
{
    extern __shared__ __align__(16) char sm[];
    const uint32_t sb = smem_u32(sm);
    const int tid = threadIdx.x, wid = tid >> 5, lane = tid & 31;
    const int g = lane >> 2, tq = lane & 3;
    const int c  = 15 - ((int)blockIdx.x >> 5);   // heavy chunks first
    const int bh = (int)blockIdx.x & 31;
    const int b = bh >> 4, h = bh & 15;
    const size_t head = (size_t)bh * L_ * HD_;
    const int wr0 = wid * 32;                     // warp's first q-row in chunk

    // Q fragments for both m16 sub-tiles; fold 1/8 * log2(e)
    const float QSCALE = 0.125f * 1.4426950408889634f;
    uint32_t qa[2][8][4];
#pragma unroll
    for (int mt2 = 0; mt2 < 2; mt2++) {
        const float* qb = g_q + head + (size_t)(c * CHUNK_ + wr0 + mt2 * 16) * HD_;
#pragma unroll
        for (int kb = 0; kb < 8; kb++) {
            const float2 lo = *(const float2*)(qb + g * 64 + kb * 8 + tq * 2);
            const float2 hi = *(const float2*)(qb + (g + 8) * 64 + kb * 8 + tq * 2);
            qa[mt2][kb][0] = __float_as_uint(lo.x * QSCALE);
            qa[mt2][kb][1] = __float_as_uint(hi.x * QSCALE);
            qa[mt2][kb][2] = __float_as_uint(lo.y * QSCALE);
            qa[mt2][kb][3] = __float_as_uint(hi.y * QSCALE);
        }
    }

    float o[2][8][4];
#pragma unroll
    for (int mt2 = 0; mt2 < 2; mt2++)
#pragma unroll
        for (int nv = 0; nv < 8; nv++)
#pragma unroll
            for (int i = 0; i < 4; i++) o[mt2][nv][i] = 0.f;
    float mr[2][2] = {{-1e30f, -1e30f}, {-1e30f, -1e30f}};
    float ls[2][2] = {{0.f, 0.f}, {0.f, 0.f}};

    // prologue: K(0) -> Kbuf0, V(0) -> Vbuf
    attn_prefetch_k(sb, g_k + head, tid);
    attn_prefetch_v(sb + AT_VOFF, g_v + head, tid);
    CP_COMMIT();

    int s = 0;
    for (int kc = 0; kc <= c; kc++) {
        CP_WAIT0();
        __syncthreads();     // KV(kc) visible

        // next K goes to the other K buffer (no reader conflict)
        if (kc < c) {
            attn_prefetch_k(sb + (uint32_t)(s ^ 1) * K_STAGE_B,
                            g_k + head + (size_t)(kc + 1) * CHUNK_ * HD_, tid);
            CP_COMMIT();
        }

        const float* Ks = (const float*)(sm + (size_t)s * K_STAGE_B);
        const float* Vs = (const float*)(sm + AT_VOFF);

#pragma unroll
        for (int hk = 0; hk < 2; hk++) {     // 64-key halves
            float sc[2][8][4];
#pragma unroll
            for (int nt = 0; nt < 8; nt++) {
                sc[0][nt][0] = sc[0][nt][1] = sc[0][nt][2] = sc[0][nt][3] = 0.f;
                sc[1][nt][0] = sc[1][nt][1] = sc[1][nt][2] = sc[1][nt][3] = 0.f;
                const float* kp = Ks + (hk * 64 + nt * 8 + g) * KS_;
#pragma unroll
                for (int kb = 0; kb < 8; kb++) {
                    const float2 bb = *(const float2*)(kp + kb * 8 + tq * 2);
                    uint32_t bfr[2];
                    bfr[0] = __float_as_uint(bb.x);
                    bfr[1] = __float_as_uint(bb.y);
                    mma8(sc[0][nt], qa[0][kb], bfr);
                    mma8(sc[1][nt], qa[1][kb], bfr);
                }
            }

#pragma unroll
            for (int mt2 = 0; mt2 < 2; mt2++) {
                float smx_lo = -1e30f, smx_hi = -1e30f;
#pragma unroll
                for (int nt = 0; nt < 8; nt++) {
                    smx_lo = fmaxf(smx_lo, fmaxf(sc[mt2][nt][0], sc[mt2][nt][1]));
                    smx_hi = fmaxf(smx_hi, fmaxf(sc[mt2][nt][2], sc[mt2][nt][3]));
                }
                smx_lo = fmaxf(smx_lo, __shfl_xor_sync(0xffffffffu, smx_lo, 1));
                smx_lo = fmaxf(smx_lo, __shfl_xor_sync(0xffffffffu, smx_lo, 2));
                smx_hi = fmaxf(smx_hi, __shfl_xor_sync(0xffffffffu, smx_hi, 1));
                smx_hi = fmaxf(smx_hi, __shfl_xor_sync(0xffffffffu, smx_hi, 2));
                const float mn_lo = fmaxf(mr[mt2][0], smx_lo);
                const float mn_hi = fmaxf(mr[mt2][1], smx_hi);
                const float corr_lo = ex2(mr[mt2][0] - mn_lo);
                const float corr_hi = ex2(mr[mt2][1] - mn_hi);
                mr[mt2][0] = mn_lo; mr[mt2][1] = mn_hi;
                ls[mt2][0] *= corr_lo; ls[mt2][1] *= corr_hi;
#pragma unroll
                for (int nt = 0; nt < 8; nt++) {
                    const float p0 = ex2(sc[mt2][nt][0] - mn_lo);
                    const float p1 = ex2(sc[mt2][nt][1] - mn_lo);
                    const float p2 = ex2(sc[mt2][nt][2] - mn_hi);
                    const float p3 = ex2(sc[mt2][nt][3] - mn_hi);
                    ls[mt2][0] += p0 + p1; ls[mt2][1] += p2 + p3;
                    sc[mt2][nt][0] = __uint_as_float(f2tf(p0));
                    sc[mt2][nt][1] = __uint_as_float(f2tf(p1));
                    sc[mt2][nt][2] = __uint_as_float(f2tf(p2));
                    sc[mt2][nt][3] = __uint_as_float(f2tf(p3));
                }
#pragma unroll
                for (int nv = 0; nv < 8; nv++) {
                    o[mt2][nv][0] *= corr_lo; o[mt2][nv][1] *= corr_lo;
                    o[mt2][nv][2] *= corr_hi; o[mt2][nv][3] *= corr_hi;
                }
            }

#pragma unroll
            for (int kb = 0; kb < 8; kb++) {
                uint32_t pa0[4], pa1[4];
                pa0[0] = __float_as_uint(sc[0][kb][0]);
                pa0[1] = __float_as_uint(sc[0][kb][2]);
                pa0[2] = __float_as_uint(sc[0][kb][1]);
                pa0[3] = __float_as_uint(sc[0][kb][3]);
                pa1[0] = __float_as_uint(sc[1][kb][0]);
                pa1[1] = __float_as_uint(sc[1][kb][2]);
                pa1[2] = __float_as_uint(sc[1][kb][1]);
                pa1[3] = __float_as_uint(sc[1][kb][3]);
#pragma unroll
                for (int nv = 0; nv < 8; nv++) {
                    const float2 vv = *(const float2*)(Vs + (nv * 8 + g) * VS_ +
                                                       hk * 64 + kb * 8 + tq * 2);
                    uint32_t vb[2];
                    vb[0] = __float_as_uint(vv.x);
                    vb[1] = __float_as_uint(vv.y);
                    mma8(o[0][nv], pa0, vb);
                    mma8(o[1][nv], pa1, vb);
                }
            }
        }

        __syncthreads();     // all warps done reading V before overwrite
        if (kc < c) {
            attn_prefetch_v(sb + AT_VOFF,
                            g_v + head + (size_t)(kc + 1) * CHUNK_, tid);
            CP_COMMIT();
        }
        s ^= 1;
    }

    // finalize + write ctx (tf32-rounded, K-permuted for out-proj)
#pragma unroll
    for (int mt2 = 0; mt2 < 2; mt2++) {
        float ll = ls[mt2][0], lh = ls[mt2][1];
        ll += __shfl_xor_sync(0xffffffffu, ll, 1);
        ll += __shfl_xor_sync(0xffffffffu, ll, 2);
        lh += __shfl_xor_sync(0xffffffffu, lh, 1);
        lh += __shfl_xor_sync(0xffffffffu, lh, 2);
        const float il = 1.f / ll, ih = 1.f / lh;
        const int r0 = c * CHUNK_ + wr0 + mt2 * 16 + g;
#pragma unroll
        for (int nv = 0; nv < 8; nv++) {
            const int col = h * HD_ + nv * 8 + 2 * tq;
            const int p0 = perm_idx(col), p1 = perm_idx(col + 1);
            float* c0 = ctx + ((size_t)b * L_ + r0) * D_;
            float* c1 = ctx + ((size_t)b * L_ + r0 + 8) * D_;
            c0[p0] = f2tff(o[mt2][nv][0] * il); c0[p1] = f2tff(o[mt2][nv][1] * il);
            c1[p0] = f2tff(o[mt2][nv][2] * ih); c1[p1] = f2tff(o[mt2][nv][3] * ih);
        }
    }
}

// ---------------------------------------------------------------------------
extern "C" void kernel_launch(void* const* d_in, const int* in_sizes, int n_in,
                              void* d_out, int out_size)
{
    const float* x    = (const float*)d_in[0];
    const float* Wqkv = (const float*)d_in[1];
    const float* bqkv = (const float*)d_in[2];
    const float* Wout = (const float*)d_in[3];
    const float* bout = (const float*)d_in[4];
    float* out = (float*)d_out;

    (void)in_sizes; (void)n_in; (void)out_size;

    cudaFuncSetAttribute(gemm_mma_kernel, cudaFuncAttributeMaxDynamicSharedMemorySize, GEMM_SMEM);
    cudaFuncSetAttribute(attn_mma_kernel, cudaFuncAttributeMaxDynamicSharedMemorySize, ATTN_SMEM);

    float *ctx_ptr, *xr, *wqkvr, *woutr;
    cudaGetSymbolAddress((void**)&ctx_ptr, g_ctx);
    cudaGetSymbolAddress((void**)&xr, g_xr);
    cudaGetSymbolAddress((void**)&wqkvr, g_wqkvr);
    cudaGetSymbolAddress((void**)&woutr, g_woutr);

    // 0. fused prep: round+permute x; transpose+round+permute both weights
    prep_kernel<<<6144, 256>>>(x, Wqkv, Wout);

    // 1. QKV projection + scatter: q/k [bh][l][perm(d)], v [bh][d][l]
    {
        dim3 grid(QKV_N / 128, M_ROWS / 64);    // (24, 64) = 1536 CTAs
        gemm_mma_kernel<<<grid, 128, GEMM_SMEM>>>(xr, wqkvr, bqkv, nullptr,
                                                  M_ROWS, QKV_N, D_, 1);
    }
    // 2. Block-causal attention -> g_ctx (permuted, tf32-rounded)
    //    1D grid: 16 chunks x 32 bh, heaviest chunks first, 2 CTAs/SM
    {
        attn_mma_kernel<<<16 * 32, 128, ATTN_SMEM>>>(ctx_ptr);
    }
    // 3. Output projection -> d_out
    {
        dim3 grid(D_ / 128, M_ROWS / 64);       // (8, 64) = 512 CTAs
        gemm_mma_kernel<<<grid, 128, GEMM_SMEM>>>(ctx_ptr, woutr, bout, out,
                                                  M_ROWS, D_, D_, 0);
    }
}

// round 16
// speedup vs baseline: 1.0039x; 1.0039x over previous
#include <cuda_runtime.h>
#include <cstdint>

// Problem constants
#define B_      2
#define L_      2048
#define D_      1024
#define H_      16
#define HD_     64
#define CHUNK_  128
#define M_ROWS  (B_ * L_)          // 4096
#define QKV_N   (3 * D_)           // 3072

// Scratch (device globals — no allocation allowed)
__device__ __align__(16) float g_q[(size_t)B_ * H_ * L_ * HD_];     // [bh][l][perm(d)]
__device__ __align__(16) float g_k[(size_t)B_ * H_ * L_ * HD_];     // [bh][l][perm(d)]
__device__ __align__(16) float g_v[(size_t)B_ * H_ * HD_ * L_];     // [bh][d][l]  (UNpermuted keys)
__device__ __align__(16) float g_ctx[(size_t)B_ * L_ * D_];         // [m][perm(c)]
__device__ __align__(16) float g_xr[(size_t)M_ROWS * D_];           // [m][perm(k)]
__device__ __align__(16) float g_wqkvr[(size_t)QKV_N * D_];         // [n][perm(k)] (transposed)
__device__ __align__(16) float g_woutr[(size_t)D_ * D_];            // [n][perm(k)] (transposed)

// ===========================================================================
// Helpers
// ===========================================================================
__device__ __forceinline__ uint32_t smem_u32(const void* p) {
    uint32_t a;
    asm("{ .reg .u64 t; cvta.to.shared.u64 t, %1; cvt.u32.u64 %0, t; }" : "=r"(a) : "l"(p));
    return a;
}
__device__ __forceinline__ uint32_t f2tf(float x) {
    uint32_t r;
    asm("cvt.rna.tf32.f32 %0, %1;" : "=r"(r) : "f"(x));
    return r;
}
__device__ __forceinline__ float f2tff(float x) { return __uint_as_float(f2tf(x)); }
__device__ __forceinline__ float ex2(float x) {
    float r;
    asm("ex2.approx.ftz.f32 %0, %1;" : "=f"(r) : "f"(x));
    return r;
}

// K-dim permutation: within each 8-group, b -> ((b&3)<<1)|(b>>2)
__device__ __forceinline__ int perm_idx(int i) {
    return (i & ~7) | ((i & 3) << 1) | ((i >> 2) & 1);
}

// m16n8k8 tf32 mma: D = A*B + D  (A row-major, B col-major)
__device__ __forceinline__ void mma8(float* c, const uint32_t* a, const uint32_t* b) {
    asm volatile(
        "mma.sync.aligned.m16n8k8.row.col.f32.tf32.tf32.f32 "
        "{%0,%1,%2,%3}, {%4,%5,%6,%7}, {%8,%9}, {%0,%1,%2,%3};"
        : "+f"(c[0]), "+f"(c[1]), "+f"(c[2]), "+f"(c[3])
        : "r"(a[0]), "r"(a[1]), "r"(a[2]), "r"(a[3]), "r"(b[0]), "r"(b[1]));
}

__device__ __forceinline__ void cp16(uint32_t dst, const void* src) {
    asm volatile("cp.async.cg.shared.global [%0], [%1], 16;" :: "r"(dst), "l"(src));
}
#define CP_COMMIT() asm volatile("cp.async.commit_group;" ::: "memory")
#define CP_WAIT0()  asm volatile("cp.async.wait_group 0;" ::: "memory")
#define CP_WAIT1()  asm volatile("cp.async.wait_group 1;" ::: "memory")

// ===========================================================================
// Fused prep kernel (unchanged from R14)
// ===========================================================================
__global__ __launch_bounds__(256) void prep_kernel(
    const float* __restrict__ x, const float* __restrict__ Wqkv,
    const float* __restrict__ Wout)
{
    __shared__ float tile[32][33];
    const int bid = blockIdx.x;
    if (bid < 2048) {
        const int i = bid * 256 + threadIdx.x;
        const float4* in = (const float4*)x;
        float4* out = (float4*)g_xr;
        const float4 a = in[2 * i], b = in[2 * i + 1];
        out[2 * i]     = make_float4(f2tff(a.x), f2tff(b.x), f2tff(a.y), f2tff(b.y));
        out[2 * i + 1] = make_float4(f2tff(a.z), f2tff(b.z), f2tff(a.w), f2tff(b.w));
        return;
    }
    const float* in;
    float* out;
    int N, bx, by;
    if (bid < 5120) {
        in = Wqkv; out = g_wqkvr; N = QKV_N;
        const int id = bid - 2048; bx = id % 96; by = id / 96;
    } else {
        in = Wout; out = g_woutr; N = D_;
        const int id = bid - 5120; bx = id % 32; by = id / 32;
    }
    const int K = D_;
    const int k0 = by * 32, n0 = bx * 32;
    const int tx = threadIdx.x & 31, ty = threadIdx.x >> 5;
#pragma unroll
    for (int i = 0; i < 4; i++)
        tile[ty + 8 * i][tx] = in[(size_t)(k0 + ty + 8 * i) * N + n0 + tx];
    __syncthreads();
    const int kp = k0 + perm_idx(tx);
#pragma unroll
    for (int i = 0; i < 4; i++)
        out[(size_t)(n0 + ty + 8 * i) * K + kp] = f2tff(tile[tx][ty + 8 * i]);
}

// ===========================================================================
// tf32 mma GEMM, templated on MT (m-tiles of 16 per CTA).
// MT=4: 64x128 CTA, 4 CTAs/SM (QKV). MT=2: 32x128 CTA, 5 CTAs/SM (out-proj).
// R14 structure: 2-stage cp.async, strength-reduced addressing, fragment
// software pipelining.
// ===========================================================================
#define GSA       40
#define GB_STG_B  (128 * 32 * 4)          // 16384

template<int MT> struct GP {
    static constexpr int A_B   = MT * 16 * GSA * 4;
    static constexpr int STG_B = A_B + GB_STG_B;
    static constexpr int SMEM  = 2 * STG_B;
};

template<int MT, int S>
__device__ __forceinline__ void gemm_prefetch(
    uint32_t adst, uint32_t bdst, const char* asrc, const char* bsrc, int koff)
{
#pragma unroll
    for (int i = 0; i < MT; i++)
        cp16(adst + S * GP<MT>::STG_B + i * (16 * GSA * 4), asrc + koff + i * (16 * D_ * 4));
#pragma unroll
    for (int i = 0; i < 8; i++)
        cp16(bdst + S * GP<MT>::STG_B + i * (16 * 128), bsrc + koff + i * (16 * D_ * 4));
}

template<int MT, int S, int KB>
__device__ __forceinline__ void load_frags(
    uint32_t af[MT][4], uint32_t bf[4][2],
    uint32_t abase, uint32_t bbase, const int* xo)
{
#pragma unroll
    for (int mt = 0; mt < MT; mt++) {
        float2 lo, hi;
        asm volatile("ld.shared.v2.f32 {%0,%1}, [%2];"
            : "=f"(lo.x), "=f"(lo.y)
            : "r"(abase + S * GP<MT>::STG_B + mt * (16 * GSA * 4) + KB * 32));
        asm volatile("ld.shared.v2.f32 {%0,%1}, [%2];"
            : "=f"(hi.x), "=f"(hi.y)
            : "r"(abase + S * GP<MT>::STG_B + mt * (16 * GSA * 4) + 8 * GSA * 4 + KB * 32));
        af[mt][0] = __float_as_uint(lo.x);
        af[mt][1] = __float_as_uint(hi.x);
        af[mt][2] = __float_as_uint(lo.y);
        af[mt][3] = __float_as_uint(hi.y);
    }
    const uint32_t bkb = bbase + (uint32_t)xo[KB];
#pragma unroll
    for (int nt = 0; nt < 4; nt++) {
        float2 bb;
        asm volatile("ld.shared.v2.f32 {%0,%1}, [%2];"
            : "=f"(bb.x), "=f"(bb.y)
            : "r"(bkb + S * GP<MT>::STG_B + nt * (8 * 128)));
        bf[nt][0] = __float_as_uint(bb.x);
        bf[nt][1] = __float_as_uint(bb.y);
    }
}

template<int MT>
__device__ __forceinline__ void mma_burst(
    float c[MT][4][4], uint32_t af[MT][4], uint32_t bf[4][2])
{
#pragma unroll
    for (int mt = 0; mt < MT; mt++)
#pragma unroll
        for (int nt = 0; nt < 4; nt++)
            mma8(c[mt][nt], af[mt], bf[nt]);
}

template<int MT, int S>
__device__ __forceinline__ void gemm_stage(
    float c[MT][4][4], uint32_t abase, uint32_t bbase, const int* xo)
{
    uint32_t af[2][MT][4], bf[2][4][2];
    load_frags<MT, S, 0>(af[0], bf[0], abase, bbase, xo);
    load_frags<MT, S, 1>(af[1], bf[1], abase, bbase, xo);
    mma_burst<MT>(c, af[0], bf[0]);
    load_frags<MT, S, 2>(af[0], bf[0], abase, bbase, xo);
    mma_burst<MT>(c, af[1], bf[1]);
    load_frags<MT, S, 3>(af[1], bf[1], abase, bbase, xo);
    mma_burst<MT>(c, af[0], bf[0]);
    mma_burst<MT>(c, af[1], bf[1]);
}

template<int MT, int OCC>
__global__ __launch_bounds__(128, OCC) void gemm_mma_kernel(
    const float* __restrict__ A, const float* __restrict__ Bt,
    const float* __restrict__ bias, float* __restrict__ C,
    int M, int N, int K, int qkv_mode)
{
    extern __shared__ __align__(16) char sm[];
    const uint32_t sb = smem_u32(sm);
    const int tid = threadIdx.x, wid = tid >> 5, lane = tid & 31;
    const int g = lane >> 2, tq = lane & 3;
    const int bm = blockIdx.y * (MT * 16), bn = blockIdx.x * 128;
    const int wn = wid * 32;

    const int pr = tid >> 3, pc = tid & 7;
    const uint32_t adst = sb + pr * (GSA * 4) + pc * 16;
    const uint32_t bdst = sb + GP<MT>::A_B + pr * 128 +
                          (uint32_t)((pc ^ ((pr & 3) << 1)) << 4);
    const char* asrc = (const char*)(A + (size_t)(bm + pr) * K) + pc * 16;
    const char* bsrc = (const char*)(Bt + (size_t)(bn + pr) * K) + pc * 16;

    const uint32_t abase = sb + (uint32_t)(g * (GSA * 4) + tq * 8);
    const uint32_t bbase = sb + GP<MT>::A_B + (uint32_t)((wn + g) * 128 +
                           ((tq >> 1) << 4) + (tq & 1) * 8);
    int xo[4];
#pragma unroll
    for (int kb = 0; kb < 4; kb++) xo[kb] = (kb ^ (g & 3)) << 5;

    float c[MT][4][4];
#pragma unroll
    for (int mt = 0; mt < MT; mt++)
#pragma unroll
        for (int nt = 0; nt < 4; nt++)
#pragma unroll
            for (int i = 0; i < 4; i++) c[mt][nt][i] = 0.f;

    const int KT = K >> 5;
    gemm_prefetch<MT, 0>(adst, bdst, asrc, bsrc, 0);   CP_COMMIT();
    gemm_prefetch<MT, 1>(adst, bdst, asrc, bsrc, 128); CP_COMMIT();

    for (int t = 0; t < KT; t += 2) {
        const int koff2 = (t + 2) * 128;
        CP_WAIT1();
        __syncthreads();
        gemm_stage<MT, 0>(c, abase, bbase, xo);
        __syncthreads();
        if (t + 2 < KT)
            gemm_prefetch<MT, 0>(adst, bdst, asrc, bsrc, koff2);
        CP_COMMIT();
        CP_WAIT1();
        __syncthreads();
        gemm_stage<MT, 1>(c, abase, bbase, xo);
        __syncthreads();
        if (t + 3 < KT)
            gemm_prefetch<MT, 1>(adst, bdst, asrc, bsrc, koff2 + 128);
        CP_COMMIT();
    }

#pragma unroll
    for (int mt = 0; mt < MT; mt++) {
#pragma unroll
        for (int nt = 0; nt < 4; nt++) {
            const int col = bn + wn + nt * 8 + 2 * tq;
            const float b0 = bias[col], b1 = bias[col + 1];
            const int r0 = bm + mt * 16 + g;
            const int r1 = r0 + 8;
            float v00 = c[mt][nt][0] + b0, v01 = c[mt][nt][1] + b1;
            float v10 = c[mt][nt][2] + b0, v11 = c[mt][nt][3] + b1;
            if (qkv_mode) {
                v00 = f2tff(v00); v01 = f2tff(v01);
                v10 = f2tff(v10); v11 = f2tff(v11);
                const int which = col >> 10;
                const int h  = (col >> 6) & 15;
                const int dd = col & 63;
                const int bh0 = (r0 >> 11) * H_ + h, l0 = r0 & 2047;
                const int bh1 = (r1 >> 11) * H_ + h, l1 = r1 & 2047;
                if (which == 2) {
                    g_v[((size_t)bh0 * HD_ + dd) * L_ + l0]     = v00;
                    g_v[((size_t)bh0 * HD_ + dd + 1) * L_ + l0] = v01;
                    g_v[((size_t)bh1 * HD_ + dd) * L_ + l1]     = v10;
                    g_v[((size_t)bh1 * HD_ + dd + 1) * L_ + l1] = v11;
                } else {
                    float* tgt = (which == 0) ? g_q : g_k;
                    const int pd0 = perm_idx(dd), pd1 = perm_idx(dd + 1);
                    float* d0 = tgt + ((size_t)bh0 * L_ + l0) * HD_;
                    float* d1 = tgt + ((size_t)bh1 * L_ + l1) * HD_;
                    d0[pd0] = v00; d0[pd1] = v01;
                    d1[pd0] = v10; d1[pd1] = v11;
                }
            } else {
                *(float2*)(C + (size_t)r0 * N + col) = make_float2(v00, v01);
                *(float2*)(C + (size_t)r1 * N + col) = make_float2(v10, v11);
            }
        }
    }
}

// ===========================================================================
// Block-causal flash attention (byte-identical to the proven R13/R14 kernel).
// 256 threads, m32 warp tiles, chunk-pair CTA, two 64-key halves,
// K/V double-buffered, one barrier per tile.
// ===========================================================================
#define KS_ 72
#define VS_ 136
#define K_STAGE_B  (128 * KS_ * 4)           // 36864
#define V_STAGE_B  (HD_ * VS_ * 4)           // 34816
#define AT_VOFF    (2 * K_STAGE_B)           // 73728
#define ATTN_SMEM  (AT_VOFF + 2 * V_STAGE_B) // 143360

__device__ __forceinline__ void attn_prefetch_kv(
    uint32_t kdst, uint32_t vdst, const float* ksrc, const float* vsrc, int tid)
{
#pragma unroll
    for (int i = 0; i < 8; i++) {
        const int idx = tid + i * 256;
        const int r = idx >> 4, c = idx & 15;
        cp16(kdst + r * (KS_ * 4) + c * 16, ksrc + r * 64 + c * 4);
    }
#pragma unroll
    for (int i = 0; i < 8; i++) {
        const int idx = tid + i * 256;
        const int r = idx >> 5, c = idx & 31;
        cp16(vdst + r * (VS_ * 4) + c * 16, vsrc + (size_t)r * L_ + c * 4);
    }
}

__global__ __launch_bounds__(256, 1) void attn_mma_kernel(float* __restrict__ ctx)
{
    extern __shared__ __align__(16) char sm[];
    const uint32_t sb = smem_u32(sm);
    const int tid = threadIdx.x, wid = tid >> 5, lane = tid & 31;
    const int g = lane >> 2, tq = lane & 3;
    const int p  = 7 - ((int)blockIdx.x >> 5);
    const int bh = (int)blockIdx.x & 31;
    const int b = bh >> 4, h = bh & 15;
    const size_t head = (size_t)bh * L_ * HD_;
    const int half = wid >> 2;
    const int my_qc = 2 * p + half;
    const int qc_hi = 2 * p + 1;
    const int wr0 = (wid & 3) * 32;

    const float QSCALE = 0.125f * 1.4426950408889634f;
    uint32_t qa[2][8][4];
#pragma unroll
    for (int mt2 = 0; mt2 < 2; mt2++) {
        const float* qb = g_q + head + (size_t)(my_qc * CHUNK_ + wr0 + mt2 * 16) * HD_;
#pragma unroll
        for (int kb = 0; kb < 8; kb++) {
            const float2 lo = *(const float2*)(qb + g * 64 + kb * 8 + tq * 2);
            const float2 hi = *(const float2*)(qb + (g + 8) * 64 + kb * 8 + tq * 2);
            qa[mt2][kb][0] = __float_as_uint(lo.x * QSCALE);
            qa[mt2][kb][1] = __float_as_uint(hi.x * QSCALE);
            qa[mt2][kb][2] = __float_as_uint(lo.y * QSCALE);
            qa[mt2][kb][3] = __float_as_uint(hi.y * QSCALE);
        }
    }

    float o[2][8][4];
#pragma unroll
    for (int mt2 = 0; mt2 < 2; mt2++)
#pragma unroll
        for (int nv = 0; nv < 8; nv++)
#pragma unroll
            for (int i = 0; i < 4; i++) o[mt2][nv][i] = 0.f;
    float mr[2][2] = {{-1e30f, -1e30f}, {-1e30f, -1e30f}};
    float ls[2][2] = {{0.f, 0.f}, {0.f, 0.f}};

    attn_prefetch_kv(sb, sb + AT_VOFF, g_k + head, g_v + head, tid);
    CP_COMMIT();

    int s = 0;
    for (int kc = 0; kc <= qc_hi; kc++) {
        CP_WAIT0();
        __syncthreads();

        if (kc < qc_hi)
            attn_prefetch_kv(sb + (uint32_t)(s ^ 1) * K_STAGE_B,
                             sb + AT_VOFF + (uint32_t)(s ^ 1) * V_STAGE_B,
                             g_k + head + (size_t)(kc + 1) * CHUNK_ * HD_,
                             g_v + head + (size_t)(kc + 1) * CHUNK_, tid);
        CP_COMMIT();

        if (kc <= my_qc) {
            const float* Ks = (const float*)(sm + (size_t)s * K_STAGE_B);
            const float* Vs = (const float*)(sm + AT_VOFF + (size_t)s * V_STAGE_B);

#pragma unroll
            for (int hk = 0; hk < 2; hk++) {
                float sc[2][8][4];
#pragma unroll
                for (int nt = 0; nt < 8; nt++) {
                    sc[0][nt][0] = sc[0][nt][1] = sc[0][nt][2] = sc[0][nt][3] = 0.f;
                    sc[1][nt][0] = sc[1][nt][1] = sc[1][nt][2] = sc[1][nt][3] = 0.f;
                    const float* kp = Ks + (hk * 64 + nt * 8 + g) * KS_;
#pragma unroll
                    for (int kb = 0; kb < 8; kb++) {
                        const float2 bb = *(const float2*)(kp + kb * 8 + tq * 2);
                        uint32_t bfr[2];
                        bfr[0] = __float_as_uint(bb.x);
                        bfr[1] = __float_as_uint(bb.y);
                        mma8(sc[0][nt], qa[0][kb], bfr);
                        mma8(sc[1][nt], qa[1][kb], bfr);
                    }
                }

#pragma unroll
                for (int mt2 = 0; mt2 < 2; mt2++) {
                    float smx_lo = -1e30f, smx_hi = -1e30f;
#pragma unroll
                    for (int nt = 0; nt < 8; nt++) {
                        smx_lo = fmaxf(smx_lo, fmaxf(sc[mt2][nt][0], sc[mt2][nt][1]));
                        smx_hi = fmaxf(smx_hi, fmaxf(sc[mt2][nt][2], sc[mt2][nt][3]));
                    }
                    smx_lo = fmaxf(smx_lo, __shfl_xor_sync(0xffffffffu, smx_lo, 1));
                    smx_lo = fmaxf(smx_lo, __shfl_xor_sync(0xffffffffu, smx_lo, 2));
                    smx_hi = fmaxf(smx_hi, __shfl_xor_sync(0xffffffffu, smx_hi, 1));
                    smx_hi = fmaxf(smx_hi, __shfl_xor_sync(0xffffffffu, smx_hi, 2));
                    const float mn_lo = fmaxf(mr[mt2][0], smx_lo);
                    const float mn_hi = fmaxf(mr[mt2][1], smx_hi);
                    const float corr_lo = ex2(mr[mt2][0] - mn_lo);
                    const float corr_hi = ex2(mr[mt2][1] - mn_hi);
                    mr[mt2][0] = mn_lo; mr[mt2][1] = mn_hi;
                    ls[mt2][0] *= corr_lo; ls[mt2][1] *= corr_hi;
#pragma unroll
                    for (int nt = 0; nt < 8; nt++) {
                        const float p0 = ex2(sc[mt2][nt][0] - mn_lo);
                        const float p1 = ex2(sc[mt2][nt][1] - mn_lo);
                        const float p2 = ex2(sc[mt2][nt][2] - mn_hi);
                        const float p3 = ex2(sc[mt2][nt][3] - mn_hi);
                        ls[mt2][0] += p0 + p1; ls[mt2][1] += p2 + p3;
                        sc[mt2][nt][0] = __uint_as_float(f2tf(p0));
                        sc[mt2][nt][1] = __uint_as_float(f2tf(p1));
                        sc[mt2][nt][2] = __uint_as_float(f2tf(p2));
                        sc[mt2][nt][3] = __uint_as_float(f2tf(p3));
                    }
#pragma unroll
                    for (int nv = 0; nv < 8; nv++) {
                        o[mt2][nv][0] *= corr_lo; o[mt2][nv][1] *= corr_lo;
                        o[mt2][nv][2] *= corr_hi; o[mt2][nv][3] *= corr_hi;
                    }
                }

#pragma unroll
                for (int kb = 0; kb < 8; kb++) {
                    uint32_t pa0[4], pa1[4];
                    pa0[0] = __float_as_uint(sc[0][kb][0]);
                    pa0[1] = __float_as_uint(sc[0][kb][2]);
                    pa0[2] = __float_as_uint(sc[0][kb][1]);
                    pa0[3] = __float_as_uint(sc[0][kb][3]);
                    pa1[0] = __float_as_uint(sc[1][kb][0]);
                    pa1[1] = __float_as_uint(sc[1][kb][2]);
                    pa1[2] = __float_as_uint(sc[1][kb][1]);
                    pa1[3] = __float_as_uint(sc[1][kb][3]);
#pragma unroll
                    for (int nv = 0; nv < 8; nv++) {
                        const float2 vv = *(const float2*)(Vs + (nv * 8 + g) * VS_ +
                                                           hk * 64 + kb * 8 + tq * 2);
                        uint32_t vb[2];
                        vb[0] = __float_as_uint(vv.x);
                        vb[1] = __float_as_uint(vv.y);
                        mma8(o[0][nv], pa0, vb);
                        mma8(o[1][nv], pa1, vb);
                    }
                }
            }
        }
        s ^= 1;
    }

#pragma unroll
    for (int mt2 = 0; mt2 < 2; mt2++) {
        float ll = ls[mt2][0], lh = ls[mt2][1];
        ll += __shfl_xor_sync(0xffffffffu, ll, 1);
        ll += __shfl_xor_sync(0xffffffffu, ll, 2);
        lh += __shfl_xor_sync(0xffffffffu, lh, 1);
        lh += __shfl_xor_sync(0xffffffffu, lh, 2);
        const float il = 1.f / ll, ih = 1.f / lh;
        const int r0 = my_qc * CHUNK_ + wr0 + mt2 * 16 + g;
#pragma unroll
        for (int nv = 0; nv < 8; nv++) {
            const int col = h * HD_ + nv * 8 + 2 * tq;
            const int p0 = perm_idx(col), p1 = perm_idx(col + 1);
            float* c0 = ctx + ((size_t)b * L_ + r0) * D_;
            float* c1 = ctx + ((size_t)b * L_ + r0 + 8) * D_;
            c0[p0] = f2tff(o[mt2][nv][0] * il); c0[p1] = f2tff(o[mt2][nv][1] * il);
            c1[p0] = f2tff(o[mt2][nv][2] * ih); c1[p1] = f2tff(o[mt2][nv][3] * ih);
        }
    }
}

// ---------------------------------------------------------------------------
extern "C" void kernel_launch(void* const* d_in, const int* in_sizes, int n_in,
                              void* d_out, int out_size)
{
    const float* x    = (const float*)d_in[0];
    const float* Wqkv = (const float*)d_in[1];
    const float* bqkv = (const float*)d_in[2];
    const float* Wout = (const float*)d_in[3];
    const float* bout = (const float*)d_in[4];
    float* out = (float*)d_out;

    (void)in_sizes; (void)n_in; (void)out_size;

    cudaFuncSetAttribute(gemm_mma_kernel<4, 4>, cudaFuncAttributeMaxDynamicSharedMemorySize, GP<4>::SMEM);
    cudaFuncSetAttribute(gemm_mma_kernel<2, 5>, cudaFuncAttributeMaxDynamicSharedMemorySize, GP<2>::SMEM);
    cudaFuncSetAttribute(attn_mma_kernel, cudaFuncAttributeMaxDynamicSharedMemorySize, ATTN_SMEM);

    float *ctx_ptr, *xr, *wqkvr, *woutr;
    cudaGetSymbolAddress((void**)&ctx_ptr, g_ctx);
    cudaGetSymbolAddress((void**)&xr, g_xr);
    cudaGetSymbolAddress((void**)&wqkvr, g_wqkvr);
    cudaGetSymbolAddress((void**)&woutr, g_woutr);

    // 0. fused prep: round+permute x; transpose+round+permute both weights
    prep_kernel<<<6144, 256>>>(x, Wqkv, Wout);

    // 1. QKV projection + scatter: q/k [bh][l][perm(d)], v [bh][d][l]
    {
        dim3 grid(QKV_N / 128, M_ROWS / 64);    // (24, 64) = 1536 CTAs
        gemm_mma_kernel<4, 4><<<grid, 128, GP<4>::SMEM>>>(xr, wqkvr, bqkv, nullptr,
                                                          M_ROWS, QKV_N, D_, 1);
    }
    // 2. Block-causal attention -> g_ctx (permuted, tf32-rounded)
    {
        attn_mma_kernel<<<8 * 32, 256, ATTN_SMEM>>>(ctx_ptr);
    }
    // 3. Output projection -> d_out  (32x128 tiles, 5 CTAs/SM)
    {
        dim3 grid(D_ / 128, M_ROWS / 32);       // (8, 128) = 1024 CTAs
        gemm_mma_kernel<2, 5><<<grid, 128, GP<2>::SMEM>>>(ctx_ptr, woutr, bout, out,
                                                          M_ROWS, D_, D_, 0);
    }
}

// round 17
// speedup vs baseline: 1.2634x; 1.2584x over previous
#include <cuda_runtime.h>
#include <cuda_fp16.h>
#include <cstdint>

// Problem constants
#define B_      2
#define L_      2048
#define D_      1024
#define H_      16
#define HD_     64
#define CHUNK_  128
#define M_ROWS  (B_ * L_)          // 4096
#define QKV_N   (3 * D_)           // 3072

// Scratch (device globals — no allocation allowed).  fp16 operand buffers.
__device__ __align__(16) __half g_qh[(size_t)B_ * H_ * L_ * HD_];    // [bh][l][perm16h(d)]
__device__ __align__(16) __half g_kh[(size_t)B_ * H_ * L_ * HD_];    // [bh][l][perm16h(d)]
__device__ __align__(16) __half g_vh[(size_t)B_ * H_ * HD_ * L_];    // [bh][d][l] natural keys
__device__ __align__(16) __half g_ctxh[(size_t)B_ * L_ * D_];        // [m][perm16h(c)]
__device__ __align__(16) __half g_xrh[(size_t)M_ROWS * D_];          // [m][perm16h(k)]
__device__ __align__(16) __half g_wqkvrh[(size_t)QKV_N * D_];        // [n][perm16h(k)]
__device__ __align__(16) __half g_woutrh[(size_t)D_ * D_];           // [n][perm16h(k)]

// ===========================================================================
// Helpers
// ===========================================================================
__device__ __forceinline__ uint32_t smem_u32(const void* p) {
    uint32_t a;
    asm("{ .reg .u64 t; cvta.to.shared.u64 t, %1; cvt.u32.u64 %0, t; }" : "=r"(a) : "l"(p));
    return a;
}
__device__ __forceinline__ float ex2(float x) {
    float r;
    asm("ex2.approx.ftz.f32 %0, %1;" : "=f"(r) : "f"(x));
    return r;
}
// fp16 pair permutation: k = G*16 + p*2 + b;  pair p -> ((p&3)<<1)|(p>>2).
// Puts pairs (tq, tq+4) adjacent so one LDS.64 yields frag regs (a0,a2).
__device__ __forceinline__ int perm16h(int i) {
    const int p = (i >> 1) & 7;
    const int pp = ((p & 3) << 1) | (p >> 2);
    return (i & ~15) | (pp << 1) | (i & 1);
}
__device__ __forceinline__ uint32_t packh2(float lo, float hi) {
    __half2 h = __floats2half2_rn(lo, hi);
    return *(uint32_t*)&h;
}

// m16n8k16 fp16 mma: D = A*B + D  (A row-major, B col-major, fp32 accum)
__device__ __forceinline__ void mma16(float* c, const uint32_t* a, const uint32_t* b) {
    asm volatile(
        "mma.sync.aligned.m16n8k16.row.col.f32.f16.f16.f32 "
        "{%0,%1,%2,%3}, {%4,%5,%6,%7}, {%8,%9}, {%0,%1,%2,%3};"
        : "+f"(c[0]), "+f"(c[1]), "+f"(c[2]), "+f"(c[3])
        : "r"(a[0]), "r"(a[1]), "r"(a[2]), "r"(a[3]), "r"(b[0]), "r"(b[1]));
}

__device__ __forceinline__ void cp16(uint32_t dst, const void* src) {
    asm volatile("cp.async.cg.shared.global [%0], [%1], 16;" :: "r"(dst), "l"(src));
}
#define CP_COMMIT() asm volatile("cp.async.commit_group;" ::: "memory")
#define CP_WAIT0()  asm volatile("cp.async.wait_group 0;" ::: "memory")
#define CP_WAIT1()  asm volatile("cp.async.wait_group 1;" ::: "memory")

// ===========================================================================
// Fused prep kernel -> fp16 operands.
//   [0, 1024)        x: round to fp16 + pair-perm (one 16-group per thread)
//   [1024, 4096)     Wqkv transpose+perm  (grid 96 x 32)
//   [4096, 5120)     Wout transpose+perm  (grid 32 x 32)
// ===========================================================================
__global__ __launch_bounds__(256) void prep_kernel(
    const float* __restrict__ x, const float* __restrict__ Wqkv,
    const float* __restrict__ Wout)
{
    __shared__ float tile[32][33];
    const int bid = blockIdx.x;
    if (bid < 1024) {
        const int i = bid * 256 + threadIdx.x;        // 16-group index
        const float4* in4 = (const float4*)x + (size_t)i * 4;
        const float4 v0 = in4[0], v1 = in4[1], v2 = in4[2], v3 = in4[3];
        const float f[16] = { v0.x, v0.y, v0.z, v0.w, v1.x, v1.y, v1.z, v1.w,
                              v2.x, v2.y, v2.z, v2.w, v3.x, v3.y, v3.z, v3.w };
        __align__(16) __half h[16];
#pragma unroll
        for (int j = 0; j < 16; j++)
            h[perm16h(j)] = __float2half_rn(f[j]);
        uint4* o = (uint4*)(g_xrh + (size_t)i * 16);
        o[0] = *(const uint4*)&h[0];
        o[1] = *(const uint4*)&h[8];
        return;
    }
    const float* in;
    __half* out;
    int N, bx, by;
    if (bid < 4096) {
        in = Wqkv; out = g_wqkvrh; N = QKV_N;
        const int id = bid - 1024; bx = id % 96; by = id / 96;
    } else {
        in = Wout; out = g_woutrh; N = D_;
        const int id = bid - 4096; bx = id % 32; by = id / 32;
    }
    const int K = D_;
    const int k0 = by * 32, n0 = bx * 32;
    const int tx = threadIdx.x & 31, ty = threadIdx.x >> 5;   // 32 x 8
#pragma unroll
    for (int i = 0; i < 4; i++)
        tile[ty + 8 * i][tx] = in[(size_t)(k0 + ty + 8 * i) * N + n0 + tx];
    __syncthreads();
    const int kp = k0 + perm16h(tx);
#pragma unroll
    for (int i = 0; i < 4; i++)
        out[(size_t)(n0 + ty + 8 * i) * K + kp] = __float2half_rn(tile[tx][ty + 8 * i]);
}

// ===========================================================================
// fp16 mma GEMM: C[M,N] = A[M,K] @ W[K,N] + bias
// A: fp16 [M][perm16h(K)], Bt: fp16 [N][perm16h(K)]. 64x128 CTA, 128 thr
// (4 warps, warp tile 64x32), BK=32, 2-stage cp.async, 4 CTAs/SM.
// Row stride 40 halves (80 B) -> all frag LDS.64 conflict-free, no swizzle.
// ===========================================================================
#define GSH       40                      // halves per smem row
#define GA_B      (64 * GSH * 2)          // 5120
#define GB_B      (128 * GSH * 2)         // 10240
#define G_STG     (GA_B + GB_B)           // 15360
#define GEMM_SMEM (2 * G_STG)             // 30720

template<int S>
__device__ __forceinline__ void gemm_prefetch(
    uint32_t adst, uint32_t bdst, const char* asrc, const char* bsrc, int koff)
{
    // lanes: r = tid>>2 (+32/iter), c = tid&3; gmem row = 2048 B (K=1024 fp16)
#pragma unroll
    for (int i = 0; i < 2; i++)           // A: 64 rows
        cp16(adst + S * G_STG + i * (32 * GSH * 2), asrc + koff + i * (32 * 2048));
#pragma unroll
    for (int i = 0; i < 4; i++)           // B: 128 rows
        cp16(bdst + S * G_STG + i * (32 * GSH * 2), bsrc + koff + i * (32 * 2048));
}

template<int S, int KB>
__device__ __forceinline__ void load_frags(
    uint32_t af[4][4], uint32_t bf[4][2], uint32_t abase, uint32_t bbase)
{
#pragma unroll
    for (int mt = 0; mt < 4; mt++) {
        uint2 lo, hi;
        asm volatile("ld.shared.v2.u32 {%0,%1}, [%2];"
            : "=r"(lo.x), "=r"(lo.y)
            : "r"(abase + S * G_STG + mt * (16 * GSH * 2) + KB * 32));
        asm volatile("ld.shared.v2.u32 {%0,%1}, [%2];"
            : "=r"(hi.x), "=r"(hi.y)
            : "r"(abase + S * G_STG + mt * (16 * GSH * 2) + 8 * GSH * 2 + KB * 32));
        af[mt][0] = lo.x; af[mt][2] = lo.y;   // row g:   k pairs tq, tq+4
        af[mt][1] = hi.x; af[mt][3] = hi.y;   // row g+8
    }
#pragma unroll
    for (int nt = 0; nt < 4; nt++) {
        uint2 bb;
        asm volatile("ld.shared.v2.u32 {%0,%1}, [%2];"
            : "=r"(bb.x), "=r"(bb.y)
            : "r"(bbase + S * G_STG + nt * (8 * GSH * 2) + KB * 32));
        bf[nt][0] = bb.x; bf[nt][1] = bb.y;
    }
}

__device__ __forceinline__ void mma_burst(
    float c[4][4][4], uint32_t af[4][4], uint32_t bf[4][2])
{
#pragma unroll
    for (int mt = 0; mt < 4; mt++)
#pragma unroll
        for (int nt = 0; nt < 4; nt++)
            mma16(c[mt][nt], af[mt], bf[nt]);
}

template<int S>
__device__ __forceinline__ void gemm_stage(
    float c[4][4][4], uint32_t abase, uint32_t bbase)
{
    uint32_t af[2][4][4], bf[2][4][2];
    load_frags<S, 0>(af[0], bf[0], abase, bbase);
    load_frags<S, 1>(af[1], bf[1], abase, bbase);
    mma_burst(c, af[0], bf[0]);
    mma_burst(c, af[1], bf[1]);
}

__global__ __launch_bounds__(128, 4) void gemm_mma_kernel(
    const __half* __restrict__ A, const __half* __restrict__ Bt,
    const float* __restrict__ bias, float* __restrict__ C,
    int M, int N, int K, int qkv_mode)
{
    extern __shared__ __align__(16) char sm[];
    const uint32_t sb = smem_u32(sm);
    const int tid = threadIdx.x, wid = tid >> 5, lane = tid & 31;
    const int g = lane >> 2, tq = lane & 3;
    const int bm = blockIdx.y * 64, bn = blockIdx.x * 128;
    const int wn = wid * 32;

    // per-lane cp bases: r = tid>>2, c = tid&3 (16B granules of 8 halves)
    const int pr = tid >> 2, pc = tid & 3;
    const uint32_t adst = sb + pr * (GSH * 2) + pc * 16;
    const uint32_t bdst = sb + GA_B + pr * (GSH * 2) + pc * 16;
    const char* asrc = (const char*)(A + (size_t)(bm + pr) * K) + pc * 16;
    const char* bsrc = (const char*)(Bt + (size_t)(bn + pr) * K) + pc * 16;

    const uint32_t abase = sb + (uint32_t)(g * (GSH * 2) + tq * 8);
    const uint32_t bbase = sb + GA_B + (uint32_t)((wn + g) * (GSH * 2) + tq * 8);

    float c[4][4][4];
#pragma unroll
    for (int mt = 0; mt < 4; mt++)
#pragma unroll
        for (int nt = 0; nt < 4; nt++)
#pragma unroll
            for (int i = 0; i < 4; i++) c[mt][nt][i] = 0.f;

    const int KT = K >> 5;                 // 32 chunks of 32 k
    gemm_prefetch<0>(adst, bdst, asrc, bsrc, 0);  CP_COMMIT();
    gemm_prefetch<1>(adst, bdst, asrc, bsrc, 64); CP_COMMIT();

    for (int t = 0; t < KT; t += 2) {
        const int koff2 = (t + 2) * 64;    // bytes along k (32 halves)
        CP_WAIT1();
        __syncthreads();
        gemm_stage<0>(c, abase, bbase);
        __syncthreads();
        if (t + 2 < KT)
            gemm_prefetch<0>(adst, bdst, asrc, bsrc, koff2);
        CP_COMMIT();
        CP_WAIT1();
        __syncthreads();
        gemm_stage<1>(c, abase, bbase);
        __syncthreads();
        if (t + 3 < KT)
            gemm_prefetch<1>(adst, bdst, asrc, bsrc, koff2 + 64);
        CP_COMMIT();
    }

    // Epilogue: c0:(g,2tq) c1:(g,2tq+1) c2:(g+8,2tq) c3:(g+8,2tq+1)
#pragma unroll
    for (int mt = 0; mt < 4; mt++) {
#pragma unroll
        for (int nt = 0; nt < 4; nt++) {
            const int col = bn + wn + nt * 8 + 2 * tq;
            const float b0 = bias[col], b1 = bias[col + 1];
            const int r0 = bm + mt * 16 + g;
            const int r1 = r0 + 8;
            const float v00 = c[mt][nt][0] + b0, v01 = c[mt][nt][1] + b1;
            const float v10 = c[mt][nt][2] + b0, v11 = c[mt][nt][3] + b1;
            if (qkv_mode) {
                const int which = col >> 10;
                const int h  = (col >> 6) & 15;
                const int dd = col & 63;
                const int bh0 = (r0 >> 11) * H_ + h, l0 = r0 & 2047;
                const int bh1 = (r1 >> 11) * H_ + h, l1 = r1 & 2047;
                if (which == 2) {
                    // V: fp16 [bh][d][l], natural key order
                    g_vh[((size_t)bh0 * HD_ + dd) * L_ + l0]     = __float2half_rn(v00);
                    g_vh[((size_t)bh0 * HD_ + dd + 1) * L_ + l0] = __float2half_rn(v01);
                    g_vh[((size_t)bh1 * HD_ + dd) * L_ + l1]     = __float2half_rn(v10);
                    g_vh[((size_t)bh1 * HD_ + dd + 1) * L_ + l1] = __float2half_rn(v11);
                } else {
                    __half* tgt = (which == 0) ? g_qh : g_kh;
                    const int pd = perm16h(dd);           // dd even -> pd even, pd+1 = perm(dd+1)
                    *(uint32_t*)(tgt + ((size_t)bh0 * L_ + l0) * HD_ + pd) = packh2(v00, v01);
                    *(uint32_t*)(tgt + ((size_t)bh1 * L_ + l1) * HD_ + pd) = packh2(v10, v11);
                }
            } else {
                *(float2*)(C + (size_t)r0 * N + col) = make_float2(v00, v01);
                *(float2*)(C + (size_t)r1 * N + col) = make_float2(v10, v11);
            }
        }
    }
}

// ===========================================================================
// Block-causal flash attention, fp16 mma (R14 structure).
// 256 threads, chunk-pair CTA, m32 warp tiles, two 64-key halves,
// K/V double-buffered, one barrier per tile. S C-frag pairs pack directly
// into the PV A-fragment (cvt.rn.f16x2) — V in natural [d][l] order.
// ===========================================================================
#define KSH        72                      // K smem row: 64 halves + pad
#define VSH        136                     // V smem row: 128 halves + pad
#define K_STG      (128 * KSH * 2)         // 18432
#define V_STG      (HD_ * VSH * 2)         // 17408
#define AT_VOFF    (2 * K_STG)             // 36864
#define ATTN_SMEM  (AT_VOFF + 2 * V_STG)   // 71680

__device__ __forceinline__ void attn_prefetch_kv(
    uint32_t kdst, uint32_t vdst, const __half* ksrc, const __half* vsrc, int tid)
{
#pragma unroll
    for (int i = 0; i < 4; i++) {          // K: 128 rows x 8 granules
        const int idx = tid + i * 256;     // 0..1023
        const int r = idx >> 3, c = idx & 7;
        cp16(kdst + r * (KSH * 2) + c * 16, (const char*)(ksrc + (size_t)r * HD_) + c * 16);
    }
#pragma unroll
    for (int i = 0; i < 4; i++) {          // V: 64 d-rows x 16 granules
        const int idx = tid + i * 256;
        const int r = idx >> 4, c = idx & 15;
        cp16(vdst + r * (VSH * 2) + c * 16, (const char*)(vsrc + (size_t)r * L_) + c * 16);
    }
}

__global__ __launch_bounds__(256, 1) void attn_mma_kernel(__half* __restrict__ ctx)
{
    extern __shared__ __align__(16) char sm[];
    const uint32_t sb = smem_u32(sm);
    const int tid = threadIdx.x, wid = tid >> 5, lane = tid & 31;
    const int g = lane >> 2, tq = lane & 3;
    const int p  = 7 - ((int)blockIdx.x >> 5);
    const int bh = (int)blockIdx.x & 31;
    const int b = bh >> 4, h = bh & 15;
    const size_t head = (size_t)bh * L_ * HD_;
    const int half = wid >> 2;
    const int my_qc = 2 * p + half;
    const int qc_hi = 2 * p + 1;
    const int wr0 = (wid & 3) * 32;

    const float QS = 0.125f * 1.4426950408889634f;   // folded into exp arg

    // Q fragments (raw, unscaled): LDG.64 supplies (a0,a2) pairs
    uint32_t qa[2][4][4];
#pragma unroll
    for (int mt2 = 0; mt2 < 2; mt2++) {
        const char* qb = (const char*)(g_qh + head +
                          (size_t)(my_qc * CHUNK_ + wr0 + mt2 * 16) * HD_);
#pragma unroll
        for (int kb = 0; kb < 4; kb++) {
            const uint2 lo = *(const uint2*)(qb + g * 128 + kb * 32 + tq * 8);
            const uint2 hi = *(const uint2*)(qb + (g + 8) * 128 + kb * 32 + tq * 8);
            qa[mt2][kb][0] = lo.x; qa[mt2][kb][2] = lo.y;
            qa[mt2][kb][1] = hi.x; qa[mt2][kb][3] = hi.y;
        }
    }

    float o[2][8][4];
#pragma unroll
    for (int mt2 = 0; mt2 < 2; mt2++)
#pragma unroll
        for (int nv = 0; nv < 8; nv++)
#pragma unroll
            for (int i = 0; i < 4; i++) o[mt2][nv][i] = 0.f;
    float mr[2][2] = {{-1e30f, -1e30f}, {-1e30f, -1e30f}};   // raw-score units
    float ls[2][2] = {{0.f, 0.f}, {0.f, 0.f}};

    attn_prefetch_kv(sb, sb + AT_VOFF, g_kh + head, g_vh + head, tid);
    CP_COMMIT();

    int s = 0;
    for (int kc = 0; kc <= qc_hi; kc++) {
        CP_WAIT0();
        __syncthreads();

        if (kc < qc_hi)
            attn_prefetch_kv(sb + (uint32_t)(s ^ 1) * K_STG,
                             sb + AT_VOFF + (uint32_t)(s ^ 1) * V_STG,
                             g_kh + head + (size_t)(kc + 1) * CHUNK_ * HD_,
                             g_vh + head + (size_t)(kc + 1) * CHUNK_, tid);
        CP_COMMIT();

        if (kc <= my_qc) {
            const char* Ksc = sm + (size_t)s * K_STG;
            const char* Vsc = sm + AT_VOFF + (size_t)s * V_STG;

#pragma unroll
            for (int hk = 0; hk < 2; hk++) {     // 64-key halves
                // S = Q K^T (m32 x n64, k64); one K frag feeds both sub-tiles
                float sc[2][8][4];
#pragma unroll
                for (int nt = 0; nt < 8; nt++) {
                    sc[0][nt][0] = sc[0][nt][1] = sc[0][nt][2] = sc[0][nt][3] = 0.f;
                    sc[1][nt][0] = sc[1][nt][1] = sc[1][nt][2] = sc[1][nt][3] = 0.f;
                    const char* kp = Ksc + (hk * 64 + nt * 8 + g) * (KSH * 2);
#pragma unroll
                    for (int kb = 0; kb < 4; kb++) {
                        const uint2 bb = *(const uint2*)(kp + kb * 32 + tq * 8);
                        uint32_t bfr[2] = { bb.x, bb.y };
                        mma16(sc[0][nt], qa[0][kb], bfr);
                        mma16(sc[1][nt], qa[1][kb], bfr);
                    }
                }

                // online softmax (raw scores; QS folded into exp args)
#pragma unroll
                for (int mt2 = 0; mt2 < 2; mt2++) {
                    float smx_lo = -1e30f, smx_hi = -1e30f;
#pragma unroll
                    for (int nt = 0; nt < 8; nt++) {
                        smx_lo = fmaxf(smx_lo, fmaxf(sc[mt2][nt][0], sc[mt2][nt][1]));
                        smx_hi = fmaxf(smx_hi, fmaxf(sc[mt2][nt][2], sc[mt2][nt][3]));
                    }
                    smx_lo = fmaxf(smx_lo, __shfl_xor_sync(0xffffffffu, smx_lo, 1));
                    smx_lo = fmaxf(smx_lo, __shfl_xor_sync(0xffffffffu, smx_lo, 2));
                    smx_hi = fmaxf(smx_hi, __shfl_xor_sync(0xffffffffu, smx_hi, 1));
                    smx_hi = fmaxf(smx_hi, __shfl_xor_sync(0xffffffffu, smx_hi, 2));
                    const float mn_lo = fmaxf(mr[mt2][0], smx_lo);
                    const float mn_hi = fmaxf(mr[mt2][1], smx_hi);
                    const float corr_lo = ex2((mr[mt2][0] - mn_lo) * QS);
                    const float corr_hi = ex2((mr[mt2][1] - mn_hi) * QS);
                    mr[mt2][0] = mn_lo; mr[mt2][1] = mn_hi;
                    ls[mt2][0] *= corr_lo; ls[mt2][1] *= corr_hi;
                    const float nm_lo = -mn_lo * QS, nm_hi = -mn_hi * QS;
#pragma unroll
                    for (int nt = 0; nt < 8; nt++) {
                        const float p0 = ex2(fmaf(sc[mt2][nt][0], QS, nm_lo));
                        const float p1 = ex2(fmaf(sc[mt2][nt][1], QS, nm_lo));
                        const float p2 = ex2(fmaf(sc[mt2][nt][2], QS, nm_hi));
                        const float p3 = ex2(fmaf(sc[mt2][nt][3], QS, nm_hi));
                        ls[mt2][0] += p0 + p1; ls[mt2][1] += p2 + p3;
                        sc[mt2][nt][0] = p0; sc[mt2][nt][1] = p1;
                        sc[mt2][nt][2] = p2; sc[mt2][nt][3] = p3;
                    }
#pragma unroll
                    for (int nv = 0; nv < 8; nv++) {
                        o[mt2][nv][0] *= corr_lo; o[mt2][nv][1] *= corr_lo;
                        o[mt2][nv][2] *= corr_hi; o[mt2][nv][3] *= corr_hi;
                    }
                }

                // O += P V (m32 x n64, 64 keys = 4 k16 groups).
                // P A-frag packed from two adjacent S n-tiles; V natural order.
#pragma unroll
                for (int kg = 0; kg < 4; kg++) {
                    uint32_t pa0[4], pa1[4];
                    pa0[0] = packh2(sc[0][2 * kg][0],     sc[0][2 * kg][1]);
                    pa0[1] = packh2(sc[0][2 * kg][2],     sc[0][2 * kg][3]);
                    pa0[2] = packh2(sc[0][2 * kg + 1][0], sc[0][2 * kg + 1][1]);
                    pa0[3] = packh2(sc[0][2 * kg + 1][2], sc[0][2 * kg + 1][3]);
                    pa1[0] = packh2(sc[1][2 * kg][0],     sc[1][2 * kg][1]);
                    pa1[1] = packh2(sc[1][2 * kg][2],     sc[1][2 * kg][3]);
                    pa1[2] = packh2(sc[1][2 * kg + 1][0], sc[1][2 * kg + 1][1]);
                    pa1[3] = packh2(sc[1][2 * kg + 1][2], sc[1][2 * kg + 1][3]);
#pragma unroll
                    for (int nv = 0; nv < 8; nv++) {
                        const char* vp = Vsc + (nv * 8 + g) * (VSH * 2) +
                                         hk * 128 + kg * 32 + tq * 4;
                        uint32_t vb[2];
                        vb[0] = *(const uint32_t*)(vp);        // keys 2tq, 2tq+1
                        vb[1] = *(const uint32_t*)(vp + 16);   // keys 2tq+8, 2tq+9
                        mma16(o[0][nv], pa0, vb);
                        mma16(o[1][nv], pa1, vb);
                    }
                }
            }
        }
        s ^= 1;
    }

    // finalize + write ctx fp16 (pair-permuted cols for the out-proj GEMM)
#pragma unroll
    for (int mt2 = 0; mt2 < 2; mt2++) {
        float ll = ls[mt2][0], lh = ls[mt2][1];
        ll += __shfl_xor_sync(0xffffffffu, ll, 1);
        ll += __shfl_xor_sync(0xffffffffu, ll, 2);
        lh += __shfl_xor_sync(0xffffffffu, lh, 1);
        lh += __shfl_xor_sync(0xffffffffu, lh, 2);
        const float il = 1.f / ll, ih = 1.f / lh;
        const int r0 = my_qc * CHUNK_ + wr0 + mt2 * 16 + g;
#pragma unroll
        for (int nv = 0; nv < 8; nv++) {
            const int col = h * HD_ + nv * 8 + 2 * tq;
            const int pd = perm16h(col);
            __half* c0 = ctx + ((size_t)b * L_ + r0) * D_;
            __half* c1 = ctx + ((size_t)b * L_ + r0 + 8) * D_;
            *(uint32_t*)(c0 + pd) = packh2(o[mt2][nv][0] * il, o[mt2][nv][1] * il);
            *(uint32_t*)(c1 + pd) = packh2(o[mt2][nv][2] * ih, o[mt2][nv][3] * ih);
        }
    }
}

// ---------------------------------------------------------------------------
extern "C" void kernel_launch(void* const* d_in, const int* in_sizes, int n_in,
                              void* d_out, int out_size)
{
    const float* x    = (const float*)d_in[0];
    const float* Wqkv = (const float*)d_in[1];
    const float* bqkv = (const float*)d_in[2];
    const float* Wout = (const float*)d_in[3];
    const float* bout = (const float*)d_in[4];
    float* out = (float*)d_out;

    (void)in_sizes; (void)n_in; (void)out_size;

    cudaFuncSetAttribute(gemm_mma_kernel, cudaFuncAttributeMaxDynamicSharedMemorySize, GEMM_SMEM);
    cudaFuncSetAttribute(attn_mma_kernel, cudaFuncAttributeMaxDynamicSharedMemorySize, ATTN_SMEM);

    __half *ctx_ptr, *xr, *wqkvr, *woutr;
    cudaGetSymbolAddress((void**)&ctx_ptr, g_ctxh);
    cudaGetSymbolAddress((void**)&xr, g_xrh);
    cudaGetSymbolAddress((void**)&wqkvr, g_wqkvrh);
    cudaGetSymbolAddress((void**)&woutr, g_woutrh);

    // 0. fused prep: fp16 round+pair-perm x; transpose+round+perm weights
    prep_kernel<<<5120, 256>>>(x, Wqkv, Wout);

    // 1. QKV projection + scatter: q/k fp16 [bh][l][perm(d)], v fp16 [bh][d][l]
    {
        dim3 grid(QKV_N / 128, M_ROWS / 64);    // (24, 64)
        gemm_mma_kernel<<<grid, 128, GEMM_SMEM>>>(xr, wqkvr, bqkv, nullptr,
                                                  M_ROWS, QKV_N, D_, 1);
    }
    // 2. Block-causal attention -> g_ctxh (fp16, pair-permuted)
    {
        attn_mma_kernel<<<8 * 32, 256, ATTN_SMEM>>>(ctx_ptr);
    }
    // 3. Output projection -> d_out (fp32)
    {
        dim3 grid(D_ / 128, M_ROWS / 64);       // (8, 64)
        gemm_mma_kernel<<<grid, 128, GEMM_SMEM>>>(ctx_ptr, woutr, bout, out,
                                                  M_ROWS, D_, D_, 0);
    }
}